// round 10
// baseline (speedup 1.0000x reference)
#include <cuda_runtime.h>
#include <math.h>

#define B_    8
#define CIN_  512
#define COUT_ 3
#define HW_   65536   // 256*256
#define ZDIM_ 512
#define GRP_  8       // channels per load batch (MLP_p1 = 8)
#define SPRE_ 12      // channels prefetched into smem pre-sync
#define SGRP_ 16      // style: ci groups (blocks) per batch

// Modulated (NOT demodulated) weights, padded float4 per ci. [B][CIN]
__device__ float4 g_ww4[B_ * CIN_];
// Partial sum-of-squares: [B][SGRP_][COUT]
__device__ float g_part[B_ * SGRP_ * COUT_];

// ---------------------------------------------------------------------------
// Kernel 1: style dense + modulate + partial demod sums.
// grid=(B, SGRP_) = 128 blocks, block=256 = 8 ci4-lanes x 32 z-slices.
// ---------------------------------------------------------------------------
__global__ __launch_bounds__(256) void style_kernel(const float* __restrict__ y,
                                                    const float* __restrict__ w,
                                                    const float* __restrict__ dense_w,
                                                    const float* __restrict__ dense_b) {
    cudaTriggerProgrammaticLaunchCompletion();  // let conv launch + prefetch now

    const int b   = blockIdx.x;
    const int gy  = blockIdx.y;          // ci group: ci in [gy*32, gy*32+32)
    const int tid = threadIdx.x;
    const int c4  = tid & 7;             // local float4 lane (4 ci each)
    const int zs  = tid >> 3;            // 0..31, z in [zs*16, zs*16+16)

    __shared__ float  sy[ZDIM_];
    __shared__ float4 sred[32][8];

    {
        const float2* y2 = reinterpret_cast<const float2*>(y + b * ZDIM_);
        const float2 v = y2[tid];
        sy[tid * 2 + 0] = v.x;
        sy[tid * 2 + 1] = v.y;
    }
    __syncthreads();

    const float4* dw4 = reinterpret_cast<const float4*>(dense_w);
    const int ci4g = gy * 8 + c4;        // global float4 column
    float4 acc = make_float4(0.f, 0.f, 0.f, 0.f);
    const int z0 = zs * 16;
#pragma unroll
    for (int zz = 0; zz < 16; ++zz) {
        const int z = z0 + zz;
        const float  yv = sy[z];
        const float4 dv = dw4[z * 128 + ci4g];
        acc.x = fmaf(yv, dv.x, acc.x);
        acc.y = fmaf(yv, dv.y, acc.y);
        acc.z = fmaf(yv, dv.z, acc.z);
        acc.w = fmaf(yv, dv.w, acc.w);
    }
    sred[zs][c4] = acc;
    __syncthreads();

#pragma unroll
    for (int off = 16; off >= 1; off >>= 1) {
        if (zs < off) {
            float4 o = sred[zs + off][c4];
            float4 m = sred[zs][c4];
            m.x += o.x; m.y += o.y; m.z += o.z; m.w += o.w;
            sred[zs][c4] = m;
        }
        __syncthreads();
    }

    if (tid < 8) {
        const float4 dot = sred[0][c4];
        const float rc  = 0.044194173824159216f;   // 1/sqrt(512)
        const int   ci0 = ci4g * 4;
        const float s[4] = {
            dot.x * rc + dense_b[ci0 + 0] + 1.0f,
            dot.y * rc + dense_b[ci0 + 1] + 1.0f,
            dot.z * rc + dense_b[ci0 + 2] + 1.0f,
            dot.w * rc + dense_b[ci0 + 3] + 1.0f };

        float q0 = 0.f, q1 = 0.f, q2 = 0.f;
#pragma unroll
        for (int j = 0; j < 4; ++j) {
            const float* wp = w + (ci0 + j) * COUT_;
            const float w0 = rc * wp[0] * s[j];
            const float w1 = rc * wp[1] * s[j];
            const float w2 = rc * wp[2] * s[j];
            g_ww4[b * CIN_ + ci0 + j] = make_float4(w0, w1, w2, 0.f);
            q0 += w0 * w0; q1 += w1 * w1; q2 += w2 * w2;
        }
#pragma unroll
        for (int off = 4; off >= 1; off >>= 1) {
            q0 += __shfl_xor_sync(0x000000FF, q0, off);
            q1 += __shfl_xor_sync(0x000000FF, q1, off);
            q2 += __shfl_xor_sync(0x000000FF, q2, off);
        }
        if (c4 == 0) {
            float* p = g_part + (b * SGRP_ + gy) * COUT_;
            p[0] = q0; p[1] = q1; p[2] = q2;
        }
    }
}

// ---------------------------------------------------------------------------
// Kernel 2: pointwise conv, HBM streaming. grid=(128, B), block=128.
// Pre-sync prefetch depth = 20 channels: ch 0-7 in registers (LDG) +
// ch 8-19 in smem (cp.async). Steady loop: 61 groups of 8 (ch 20..507),
// 4-channel epilogue (ch 508..511). Demod applied at the end.
// ---------------------------------------------------------------------------
__global__ __launch_bounds__(128, 7) void conv_kernel(const float* __restrict__ x,
                                                      float* __restrict__ out) {
    const int b    = blockIdx.y;
    const int pix4 = blockIdx.x * 128 + threadIdx.x;  // 0 .. HW/4-1

    const float4* xb = reinterpret_cast<const float4*>(
                           x + (size_t)b * CIN_ * HW_) + pix4;

    __shared__ float4 spre[SPRE_][128];  // ch 8..19 prefetch (24 KB)
    __shared__ float  sw0[CIN_], sw1[CIN_], sw2[CIN_];
    __shared__ float  sd[COUT_];

    // ---- weight-independent prefetch (overlaps style via PDL) ----
    float4 buf[GRP_];
#pragma unroll
    for (int j = 0; j < GRP_; ++j)
        buf[j] = xb[(size_t)j * (HW_ / 4)];
    {
        unsigned sbase;
        asm("{ .reg .u64 t; cvta.to.shared.u64 t, %1; cvt.u32.u64 %0, t; }"
            : "=r"(sbase) : "l"(&spre[0][threadIdx.x]));
#pragma unroll
        for (int j = 0; j < SPRE_; ++j) {
            const float4* src = &xb[(size_t)(GRP_ + j) * (HW_ / 4)];
            asm volatile("cp.async.cg.shared.global [%0], [%1], 16;"
                         :: "r"(sbase + j * 128 * 16), "l"(src));
        }
        asm volatile("cp.async.commit_group;");
    }

    cudaGridDependencySynchronize();   // wait for style_kernel

    if (threadIdx.x < COUT_) {
        const float* p = g_part + b * SGRP_ * COUT_ + threadIdx.x;
        float q = 0.f;
#pragma unroll
        for (int k = 0; k < SGRP_; ++k) q += p[k * COUT_];
        sd[threadIdx.x] = rsqrtf(q + 1e-8f);
    }
    for (int i = threadIdx.x; i < CIN_; i += 128) {
        const float4 wv = g_ww4[b * CIN_ + i];
        sw0[i] = wv.x; sw1[i] = wv.y; sw2[i] = wv.z;
    }
    asm volatile("cp.async.wait_group 0;");
    __syncthreads();

    float4 a0 = make_float4(0.f, 0.f, 0.f, 0.f);
    float4 a1 = make_float4(0.f, 0.f, 0.f, 0.f);
    float4 a2 = make_float4(0.f, 0.f, 0.f, 0.f);

#define FMA1(CI, V)                                                     \
    do {                                                                 \
        const float4 v  = (V);                                           \
        const float  w0 = sw0[CI];                                       \
        const float  w1 = sw1[CI];                                       \
        const float  w2 = sw2[CI];                                       \
        a0.x = fmaf(w0, v.x, a0.x); a0.y = fmaf(w0, v.y, a0.y);          \
        a0.z = fmaf(w0, v.z, a0.z); a0.w = fmaf(w0, v.w, a0.w);          \
        a1.x = fmaf(w1, v.x, a1.x); a1.y = fmaf(w1, v.y, a1.y);          \
        a1.z = fmaf(w1, v.z, a1.z); a1.w = fmaf(w1, v.w, a1.w);          \
        a2.x = fmaf(w2, v.x, a2.x); a2.y = fmaf(w2, v.y, a2.y);          \
        a2.z = fmaf(w2, v.z, a2.z); a2.w = fmaf(w2, v.w, a2.w);          \
    } while (0)

    // consume ch 0-7 (regs), then issue reg loads for ch 20-27
#pragma unroll
    for (int j = 0; j < GRP_; ++j) FMA1(j, buf[j]);
#pragma unroll
    for (int j = 0; j < GRP_; ++j)
        buf[j] = xb[(size_t)(GRP_ + SPRE_ + j) * (HW_ / 4)];

    // consume ch 8-19 (smem prefetch) while ch 20-27 is in flight
#pragma unroll
    for (int j = 0; j < SPRE_; ++j) FMA1(GRP_ + j, spre[j][threadIdx.x]);

    // steady state: 61 full groups covering ch 20..507
    int base = GRP_ + SPRE_;             // 20
    for (int g = 0; g < 61; ++g) {
#pragma unroll
        for (int j = 0; j < GRP_; ++j) FMA1(base + j, buf[j]);
        const int nb = base + GRP_;
        if (g < 60) {
#pragma unroll
            for (int j = 0; j < GRP_; ++j)
                buf[j] = xb[(size_t)(nb + j) * (HW_ / 4)];
        } else {
#pragma unroll
            for (int j = 0; j < 4; ++j)
                buf[j] = xb[(size_t)(nb + j) * (HW_ / 4)];
        }
        base = nb;
    }
    // epilogue: ch 508-511
#pragma unroll
    for (int j = 0; j < 4; ++j) FMA1(base + j, buf[j]);
#undef FMA1

    const float d0 = sd[0], d1 = sd[1], d2 = sd[2];
    a0.x *= d0; a0.y *= d0; a0.z *= d0; a0.w *= d0;
    a1.x *= d1; a1.y *= d1; a1.z *= d1; a1.w *= d1;
    a2.x *= d2; a2.y *= d2; a2.z *= d2; a2.w *= d2;

    float4* ob = reinterpret_cast<float4*>(out + (size_t)b * COUT_ * HW_);
    ob[0 * (HW_ / 4) + pix4] = a0;
    ob[1 * (HW_ / 4) + pix4] = a1;
    ob[2 * (HW_ / 4) + pix4] = a2;
}

// ---------------------------------------------------------------------------
// Inputs: x, y, w, dense_w, dense_b. Output: float [8,3,256,256]
// ---------------------------------------------------------------------------
extern "C" void kernel_launch(void* const* d_in, const int* in_sizes, int n_in,
                              void* d_out, int out_size) {
    const float* x       = (const float*)d_in[0];
    const float* y       = (const float*)d_in[1];
    const float* w       = (const float*)d_in[2];
    const float* dense_w = (const float*)d_in[3];
    const float* dense_b = (const float*)d_in[4];
    float* out = (float*)d_out;

    dim3 sgrid(B_, SGRP_);
    style_kernel<<<sgrid, 256>>>(y, w, dense_w, dense_b);

    cudaLaunchConfig_t cfg = {};
    cfg.gridDim  = dim3(HW_ / 4 / 128, B_);
    cfg.blockDim = dim3(128);
    cfg.dynamicSmemBytes = 0;
    cfg.stream = 0;
    cudaLaunchAttribute attrs[1];
    attrs[0].id = cudaLaunchAttributeProgrammaticStreamSerialization;
    attrs[0].val.programmaticStreamSerializationAllowed = 1;
    cfg.attrs = attrs;
    cfg.numAttrs = 1;
    cudaLaunchKernelEx(&cfg, conv_kernel, x, out);
}

// round 11
// speedup vs baseline: 1.2244x; 1.2244x over previous
#include <cuda_runtime.h>
#include <math.h>

#define B_    8
#define CIN_  512
#define COUT_ 3
#define HW_   65536   // 256*256
#define ZDIM_ 512
#define GRP_  8       // channels per load batch (MLP_p1 = 8)
#define SGRP_ 16      // style: ci groups (blocks) per batch

// Modulated (NOT demodulated) weights, padded float4 per ci. [B][CIN]
__device__ float4 g_ww4[B_ * CIN_];
// Partial sum-of-squares: [B][SGRP_][COUT]
__device__ float g_part[B_ * SGRP_ * COUT_];

// ---------------------------------------------------------------------------
// Kernel 1: style dense + modulate + partial demod sums.
// grid=(B, SGRP_) = 128 blocks, block=256 = 8 ci4-lanes x 32 z-slices.
// Each block covers 32 channels; dense_w pulled by 128 SMs in parallel.
// ---------------------------------------------------------------------------
__global__ __launch_bounds__(256) void style_kernel(const float* __restrict__ y,
                                                    const float* __restrict__ w,
                                                    const float* __restrict__ dense_w,
                                                    const float* __restrict__ dense_b) {
    cudaTriggerProgrammaticLaunchCompletion();  // let conv launch + prefetch now

    const int b   = blockIdx.x;
    const int gy  = blockIdx.y;          // ci group: ci in [gy*32, gy*32+32)
    const int tid = threadIdx.x;
    const int c4  = tid & 7;             // local float4 lane (4 ci each)
    const int zs  = tid >> 3;            // 0..31, z in [zs*16, zs*16+16)

    __shared__ float  sy[ZDIM_];
    __shared__ float4 sred[32][8];

    {
        const float2* y2 = reinterpret_cast<const float2*>(y + b * ZDIM_);
        const float2 v = y2[tid];
        sy[tid * 2 + 0] = v.x;
        sy[tid * 2 + 1] = v.y;
    }
    __syncthreads();

    // partial dot over 16 z for 4 consecutive ci — independent float4 loads
    const float4* dw4 = reinterpret_cast<const float4*>(dense_w);
    const int ci4g = gy * 8 + c4;        // global float4 column
    float4 acc = make_float4(0.f, 0.f, 0.f, 0.f);
    const int z0 = zs * 16;
#pragma unroll
    for (int zz = 0; zz < 16; ++zz) {
        const int z = z0 + zz;
        const float  yv = sy[z];
        const float4 dv = dw4[z * 128 + ci4g];
        acc.x = fmaf(yv, dv.x, acc.x);
        acc.y = fmaf(yv, dv.y, acc.y);
        acc.z = fmaf(yv, dv.z, acc.z);
        acc.w = fmaf(yv, dv.w, acc.w);
    }
    sred[zs][c4] = acc;
    __syncthreads();

    // tree-reduce over the 32 z-slices
#pragma unroll
    for (int off = 16; off >= 1; off >>= 1) {
        if (zs < off) {
            float4 o = sred[zs + off][c4];
            float4 m = sred[zs][c4];
            m.x += o.x; m.y += o.y; m.z += o.z; m.w += o.w;
            sred[zs][c4] = m;
        }
        __syncthreads();
    }

    if (tid < 8) {
        const float4 dot = sred[0][c4];
        const float rc  = 0.044194173824159216f;   // 1/sqrt(512)
        const int   ci0 = ci4g * 4;
        const float s[4] = {
            dot.x * rc + dense_b[ci0 + 0] + 1.0f,
            dot.y * rc + dense_b[ci0 + 1] + 1.0f,
            dot.z * rc + dense_b[ci0 + 2] + 1.0f,
            dot.w * rc + dense_b[ci0 + 3] + 1.0f };

        float q0 = 0.f, q1 = 0.f, q2 = 0.f;
#pragma unroll
        for (int j = 0; j < 4; ++j) {
            const float* wp = w + (ci0 + j) * COUT_;
            const float w0 = rc * wp[0] * s[j];
            const float w1 = rc * wp[1] * s[j];
            const float w2 = rc * wp[2] * s[j];
            g_ww4[b * CIN_ + ci0 + j] = make_float4(w0, w1, w2, 0.f);
            q0 += w0 * w0; q1 += w1 * w1; q2 += w2 * w2;
        }
        // reduce over the 8 active lanes (all in warp 0)
#pragma unroll
        for (int off = 4; off >= 1; off >>= 1) {
            q0 += __shfl_xor_sync(0x000000FF, q0, off);
            q1 += __shfl_xor_sync(0x000000FF, q1, off);
            q2 += __shfl_xor_sync(0x000000FF, q2, off);
        }
        if (c4 == 0) {
            float* p = g_part + (b * SGRP_ + gy) * COUT_;
            p[0] = q0; p[1] = q1; p[2] = q2;
        }
    }
}

// ---------------------------------------------------------------------------
// Kernel 2: pointwise conv, HBM streaming. grid=(128, B), block=128.
// GRP_=8 load batching (MLP_p1=8). Pre-sync prefetch depth = 16 channels:
// group 0 in registers (LDG) + group 1 in smem (cp.async, zero reg cost).
// smem = 23 KB/block -> 7 blocks/SM -> single wave (1024 <= 1036). Do NOT
// grow smem: 31 KB drops to 6 blocks/SM, breaks the wave (R10: 71% DRAM).
// Demod factor computed per-block from partial sums, applied at end.
// ---------------------------------------------------------------------------
__global__ __launch_bounds__(128, 7) void conv_kernel(const float* __restrict__ x,
                                                      float* __restrict__ out) {
    const int b    = blockIdx.y;
    const int pix4 = blockIdx.x * 128 + threadIdx.x;  // 0 .. HW/4-1

    const float4* xb = reinterpret_cast<const float4*>(
                           x + (size_t)b * CIN_ * HW_) + pix4;

    __shared__ float4 spre[GRP_][128];   // group-1 prefetch (16 KB)
    __shared__ float  sw0[CIN_], sw1[CIN_], sw2[CIN_];
    __shared__ float  sd[COUT_];

    // ---- weight-independent prefetch (overlaps style via PDL) ----
    // group 0 -> registers
    float4 buf[GRP_];
#pragma unroll
    for (int j = 0; j < GRP_; ++j)
        buf[j] = xb[(size_t)j * (HW_ / 4)];
    // group 1 -> smem via cp.async (no register cost)
    {
        unsigned sbase;
        asm("{ .reg .u64 t; cvta.to.shared.u64 t, %1; cvt.u32.u64 %0, t; }"
            : "=r"(sbase) : "l"(&spre[0][threadIdx.x]));
#pragma unroll
        for (int j = 0; j < GRP_; ++j) {
            const float4* src = &xb[(size_t)(GRP_ + j) * (HW_ / 4)];
            asm volatile("cp.async.cg.shared.global [%0], [%1], 16;"
                         :: "r"(sbase + j * 128 * 16), "l"(src));
        }
        asm volatile("cp.async.commit_group;");
    }

    cudaGridDependencySynchronize();   // wait for style_kernel

    if (threadIdx.x < COUT_) {
        const float* p = g_part + b * SGRP_ * COUT_ + threadIdx.x;
        float q = 0.f;
#pragma unroll
        for (int k = 0; k < SGRP_; ++k) q += p[k * COUT_];
        sd[threadIdx.x] = rsqrtf(q + 1e-8f);
    }
    for (int i = threadIdx.x; i < CIN_; i += 128) {
        const float4 wv = g_ww4[b * CIN_ + i];
        sw0[i] = wv.x; sw1[i] = wv.y; sw2[i] = wv.z;
    }
    asm volatile("cp.async.wait_group 0;");
    __syncthreads();

    float4 a0 = make_float4(0.f, 0.f, 0.f, 0.f);
    float4 a1 = make_float4(0.f, 0.f, 0.f, 0.f);
    float4 a2 = make_float4(0.f, 0.f, 0.f, 0.f);

#define FMA_GROUP(ci0, VGET)                                            \
    _Pragma("unroll")                                                    \
    for (int j = 0; j < GRP_; ++j) {                                     \
        const float4 v  = VGET;                                          \
        const float  w0 = sw0[(ci0) + j];                                \
        const float  w1 = sw1[(ci0) + j];                                \
        const float  w2 = sw2[(ci0) + j];                                \
        a0.x = fmaf(w0, v.x, a0.x); a0.y = fmaf(w0, v.y, a0.y);          \
        a0.z = fmaf(w0, v.z, a0.z); a0.w = fmaf(w0, v.w, a0.w);          \
        a1.x = fmaf(w1, v.x, a1.x); a1.y = fmaf(w1, v.y, a1.y);          \
        a1.z = fmaf(w1, v.z, a1.z); a1.w = fmaf(w1, v.w, a1.w);          \
        a2.x = fmaf(w2, v.x, a2.x); a2.y = fmaf(w2, v.y, a2.y);          \
        a2.z = fmaf(w2, v.z, a2.z); a2.w = fmaf(w2, v.w, a2.w);          \
    }

    // consume group 0 (regs), issue loads for group 2
    FMA_GROUP(0, buf[j])
#pragma unroll
    for (int j = 0; j < GRP_; ++j)
        buf[j] = xb[(size_t)(2 * GRP_ + j) * (HW_ / 4)];

    // consume group 1 (smem prefetch) while group 2 is in flight
    FMA_GROUP(GRP_, spre[j][threadIdx.x])

    // steady state: groups 2..63
    for (int g = 2; g < CIN_ / GRP_; ++g) {
        const int ci0 = g * GRP_;
        FMA_GROUP(ci0, buf[j])
        if (g + 1 < CIN_ / GRP_) {
            const int cn = ci0 + GRP_;
#pragma unroll
            for (int j = 0; j < GRP_; ++j)
                buf[j] = xb[(size_t)(cn + j) * (HW_ / 4)];
        }
    }
#undef FMA_GROUP

    const float d0 = sd[0], d1 = sd[1], d2 = sd[2];
    a0.x *= d0; a0.y *= d0; a0.z *= d0; a0.w *= d0;
    a1.x *= d1; a1.y *= d1; a1.z *= d1; a1.w *= d1;
    a2.x *= d2; a2.y *= d2; a2.z *= d2; a2.w *= d2;

    float4* ob = reinterpret_cast<float4*>(out + (size_t)b * COUT_ * HW_);
    ob[0 * (HW_ / 4) + pix4] = a0;
    ob[1 * (HW_ / 4) + pix4] = a1;
    ob[2 * (HW_ / 4) + pix4] = a2;
}

// ---------------------------------------------------------------------------
// Inputs: x, y, w, dense_w, dense_b. Output: float [8,3,256,256]
// ---------------------------------------------------------------------------
extern "C" void kernel_launch(void* const* d_in, const int* in_sizes, int n_in,
                              void* d_out, int out_size) {
    const float* x       = (const float*)d_in[0];
    const float* y       = (const float*)d_in[1];
    const float* w       = (const float*)d_in[2];
    const float* dense_w = (const float*)d_in[3];
    const float* dense_b = (const float*)d_in[4];
    float* out = (float*)d_out;

    dim3 sgrid(B_, SGRP_);
    style_kernel<<<sgrid, 256>>>(y, w, dense_w, dense_b);

    cudaLaunchConfig_t cfg = {};
    cfg.gridDim  = dim3(HW_ / 4 / 128, B_);
    cfg.blockDim = dim3(128);
    cfg.dynamicSmemBytes = 0;
    cfg.stream = 0;
    cudaLaunchAttribute attrs[1];
    attrs[0].id = cudaLaunchAttributeProgrammaticStreamSerialization;
    attrs[0].val.programmaticStreamSerializationAllowed = 1;
    cfg.attrs = attrs;
    cfg.numAttrs = 1;
    cudaLaunchKernelEx(&cfg, conv_kernel, x, out);
}